// round 1
// baseline (speedup 1.0000x reference)
#include <cuda_runtime.h>
#include <cuda_fp16.h>

#define N 8192
#define ITERS 10
#define EPSC 1e-8f

// ---- static device scratch (no allocations allowed) ----
// E = exp(W) stored as fp16: 8192*8192*2 = 128 MiB
__device__ __align__(16) __half2 g_E[(size_t)N * N / 2];
__device__ __align__(16) float g_r[N];
__device__ __align__(16) float g_c[N];
__device__ __align__(16) float g_tpart[32][N];   // column partial sums (deterministic reduce)

struct alignas(16) H8 { __half2 h[4]; };         // 8 halves = 16B vector

// ---------------- init r = c = 1 ----------------
__global__ void k_init() {
    int j = blockIdx.x * 256 + threadIdx.x;
    g_r[j] = 1.0f;
    g_c[j] = 1.0f;
}

// ---------------- E = exp(W) via FFMA polynomial (MUFU-free) ----------------
// exp(x) = sum_{k=0..8} (e^0.5 / k!) * (x-0.5)^k ; |x-0.5| <= ~0.58 -> abs err ~5e-8
__device__ __forceinline__ float exp_poly(float x) {
    const float C0 = 1.6487212707001282f;
    const float C1 = 1.6487212707001282f;
    const float C2 = 0.8243606353500641f;
    const float C3 = 0.27478687845002137f;
    const float C4 = 0.06869671961250534f;
    const float C5 = 0.013739343922501068f;
    const float C6 = 0.0022898906537501780f;
    const float C7 = 0.00032712723625002546f;
    const float C8 = 0.000040890904531253183f;
    float t = x - 0.5f;
    float p = C8;
    p = fmaf(p, t, C7);
    p = fmaf(p, t, C6);
    p = fmaf(p, t, C5);
    p = fmaf(p, t, C4);
    p = fmaf(p, t, C3);
    p = fmaf(p, t, C2);
    p = fmaf(p, t, C1);
    p = fmaf(p, t, C0);
    return p;
}

__global__ void k_exp(const float* __restrict__ W) {
    size_t base = ((size_t)blockIdx.x * 256 + threadIdx.x) * 8;
    float4 a = *reinterpret_cast<const float4*>(W + base);
    float4 b = *reinterpret_cast<const float4*>(W + base + 4);
    H8 v;
    v.h[0] = __floats2half2_rn(exp_poly(a.x), exp_poly(a.y));
    v.h[1] = __floats2half2_rn(exp_poly(a.z), exp_poly(a.w));
    v.h[2] = __floats2half2_rn(exp_poly(b.x), exp_poly(b.y));
    v.h[3] = __floats2half2_rn(exp_poly(b.z), exp_poly(b.w));
    reinterpret_cast<H8*>(g_E)[base / 8] = v;
}

// ---------------- row pass: s_i = sum_j E_ij * c_j ; r_i update ----------------
__global__ void k_row() {
    int i = blockIdx.x;
    const H8* row = reinterpret_cast<const H8*>(g_E + (size_t)i * (N / 2));
    float acc = 0.0f;
    #pragma unroll
    for (int k = threadIdx.x; k < N / 8; k += 256) {
        H8 v = row[k];
        float4 c0 = *reinterpret_cast<const float4*>(g_c + k * 8);
        float4 c1 = *reinterpret_cast<const float4*>(g_c + k * 8 + 4);
        float2 f0 = __half22float2(v.h[0]);
        float2 f1 = __half22float2(v.h[1]);
        float2 f2 = __half22float2(v.h[2]);
        float2 f3 = __half22float2(v.h[3]);
        acc += f0.x * c0.x + f0.y * c0.y + f1.x * c0.z + f1.y * c0.w;
        acc += f2.x * c1.x + f2.y * c1.y + f3.x * c1.z + f3.y * c1.w;
    }
    // block reduce (8 warps)
    #pragma unroll
    for (int o = 16; o > 0; o >>= 1) acc += __shfl_down_sync(0xffffffffu, acc, o);
    __shared__ float sm[8];
    int lane = threadIdx.x & 31, wid = threadIdx.x >> 5;
    if (lane == 0) sm[wid] = acc;
    __syncthreads();
    if (threadIdx.x == 0) {
        float s = 0.0f;
        #pragma unroll
        for (int w = 0; w < 8; w++) s += sm[w];
        float r = g_r[i];
        g_r[i] = r / (r * s + EPSC);
    }
}

// ---------------- col pass: partial t_j = sum_i r_i * E_ij over a 256-row chunk ----------------
// grid (32 strips of 256 cols, 32 chunks of 256 rows), 128 threads (2 cols/thread via half2)
__global__ void k_col() {
    int j2 = blockIdx.x * 128 + threadIdx.x;       // half2 column index
    int i0 = blockIdx.y * 256;
    __shared__ float rs[256];
    rs[threadIdx.x]        = g_r[i0 + threadIdx.x];
    rs[threadIdx.x + 128]  = g_r[i0 + threadIdx.x + 128];
    __syncthreads();
    const __half2* base = g_E + (size_t)i0 * (N / 2) + j2;
    float ax = 0.0f, ay = 0.0f;
    #pragma unroll 8
    for (int i = 0; i < 256; i++) {
        float rv = rs[i];
        float2 e = __half22float2(base[(size_t)i * (N / 2)]);
        ax = fmaf(rv, e.x, ax);
        ay = fmaf(rv, e.y, ay);
    }
    float2 outv = make_float2(ax, ay);
    reinterpret_cast<float2*>(g_tpart[blockIdx.y])[j2] = outv;
}

// ---------------- deterministic column reduce + c update ----------------
__global__ void k_creduce() {
    int j = blockIdx.x * 256 + threadIdx.x;
    float t = 0.0f;
    #pragma unroll
    for (int k = 0; k < 32; k++) t += g_tpart[k][j];
    float cv = g_c[j];
    g_c[j] = cv / (cv * t + EPSC);
}

// ---------------- final: out_ij = r_i * E_ij * c_j ----------------
__global__ void k_final(float* __restrict__ out) {
    size_t base = ((size_t)blockIdx.x * 256 + threadIdx.x) * 8;
    int i = (int)(base >> 13);        // row (8192 cols)
    int j = (int)(base & (N - 1));    // col start (row-aligned: 8 | 8192)
    float r = g_r[i];
    H8 v = *reinterpret_cast<const H8*>(g_E + base / 2);
    float4 c0 = *reinterpret_cast<const float4*>(g_c + j);
    float4 c1 = *reinterpret_cast<const float4*>(g_c + j + 4);
    float2 f0 = __half22float2(v.h[0]);
    float2 f1 = __half22float2(v.h[1]);
    float2 f2 = __half22float2(v.h[2]);
    float2 f3 = __half22float2(v.h[3]);
    float4 o0, o1;
    o0.x = r * f0.x * c0.x;  o0.y = r * f0.y * c0.y;
    o0.z = r * f1.x * c0.z;  o0.w = r * f1.y * c0.w;
    o1.x = r * f2.x * c1.x;  o1.y = r * f2.y * c1.y;
    o1.z = r * f3.x * c1.z;  o1.w = r * f3.y * c1.w;
    *reinterpret_cast<float4*>(out + base)     = o0;
    *reinterpret_cast<float4*>(out + base + 4) = o1;
}

extern "C" void kernel_launch(void* const* d_in, const int* in_sizes, int n_in,
                              void* d_out, int out_size) {
    const float* W = (const float*)d_in[0];
    float* out = (float*)d_out;
    (void)in_sizes; (void)n_in; (void)out_size;

    const int ELEM_BLOCKS = (int)(((size_t)N * N) / (256 * 8));  // 32768

    k_init<<<N / 256, 256>>>();
    k_exp<<<ELEM_BLOCKS, 256>>>(W);
    for (int it = 0; it < ITERS; it++) {
        k_row<<<N, 256>>>();
        k_col<<<dim3(32, 32), 128>>>();
        k_creduce<<<N / 256, 256>>>();
    }
    k_final<<<ELEM_BLOCKS, 256>>>(out);
}

// round 2
// speedup vs baseline: 1.1920x; 1.1920x over previous
#include <cuda_runtime.h>
#include <cuda_fp16.h>

#define N 8192
#define N8 (N / 8)          // 1024 float4 (H8) per row
#define ITERS 10
#define EPSC 1e-8f
#define NCHUNK 256          // 32 rows per chunk in col pass

// ---- static device scratch (no allocations allowed) ----
__device__ __align__(16) __half2 g_E[(size_t)N * N / 2];   // 128 MiB fp16 exp(W)
__device__ __align__(16) float g_r[N];
__device__ __align__(16) float g_c[N];
__device__ __align__(16) float g_tpart[NCHUNK][N];         // col partials (8 MB)
__device__ __align__(16) float g_t2[16][N];                // stage-2 col partials
__device__ __align__(16) float g_spart[4][N];              // row-sum partials (exp fusion)

// ---------------- exp(x) poly around 0.5, pure FFMA (MUFU-free) ----------------
// x in [-0.06, 1.06]; abs err ~5e-8, far below fp16 ulp
__device__ __forceinline__ float exp_poly(float x) {
    const float C0 = 1.6487212707001282f;
    const float C1 = 1.6487212707001282f;
    const float C2 = 0.8243606353500641f;
    const float C3 = 0.27478687845002137f;
    const float C4 = 0.06869671961250534f;
    const float C5 = 0.013739343922501068f;
    const float C6 = 0.0022898906537501780f;
    const float C7 = 0.00032712723625002546f;
    const float C8 = 0.000040890904531253183f;
    float t = x - 0.5f;
    float p = C8;
    p = fmaf(p, t, C7);
    p = fmaf(p, t, C6);
    p = fmaf(p, t, C5);
    p = fmaf(p, t, C4);
    p = fmaf(p, t, C3);
    p = fmaf(p, t, C2);
    p = fmaf(p, t, C1);
    p = fmaf(p, t, C0);
    return p;
}

// ---------------- E = exp(W), fused with row-1 partial sums (c == 1) ----------------
// block = 2048 contiguous elems = quarter of a row. row = blockIdx>>2, q = blockIdx&3.
__global__ void __launch_bounds__(256) k_exp(const float* __restrict__ W) {
    size_t base = ((size_t)blockIdx.x * 256 + threadIdx.x) * 8;
    float4 a = __ldcs(reinterpret_cast<const float4*>(W + base));
    float4 b = __ldcs(reinterpret_cast<const float4*>(W + base + 4));
    float4 packed;
    __half2* h = reinterpret_cast<__half2*>(&packed);
    h[0] = __floats2half2_rn(exp_poly(a.x), exp_poly(a.y));
    h[1] = __floats2half2_rn(exp_poly(a.z), exp_poly(a.w));
    h[2] = __floats2half2_rn(exp_poly(b.x), exp_poly(b.y));
    h[3] = __floats2half2_rn(exp_poly(b.z), exp_poly(b.w));
    __stcs(reinterpret_cast<float4*>(g_E) + base / 8, packed);

    // row-sum partial from the ROUNDED half values (consistent with later passes)
    float2 f0 = __half22float2(h[0]);
    float2 f1 = __half22float2(h[1]);
    float2 f2 = __half22float2(h[2]);
    float2 f3 = __half22float2(h[3]);
    float s = (f0.x + f0.y) + (f1.x + f1.y) + (f2.x + f2.y) + (f3.x + f3.y);

    __shared__ float sm[8];
    #pragma unroll
    for (int o = 16; o > 0; o >>= 1) s += __shfl_down_sync(0xffffffffu, s, o);
    int lane = threadIdx.x & 31, wid = threadIdx.x >> 5;
    if (lane == 0) sm[wid] = s;
    __syncthreads();
    if (threadIdx.x == 0) {
        float t = 0.0f;
        #pragma unroll
        for (int w = 0; w < 8; w++) t += sm[w];
        g_spart[blockIdx.x & 3][blockIdx.x >> 2] = t;
    }
}

// ---------------- r1 = 1/(rowsum + eps);  c = 1 ----------------
__global__ void k_r1() {
    int j = blockIdx.x * 256 + threadIdx.x;
    float s = g_spart[0][j] + g_spart[1][j] + g_spart[2][j] + g_spart[3][j];
    g_r[j] = 1.0f / (s + EPSC);
    g_c[j] = 1.0f;
}

// ---------------- row pass: s_i = sum_j E_ij c_j ; r update ----------------
// one row per 128-thread block, 8 fully-unrolled 16B E loads + 32B c loads
__global__ void __launch_bounds__(128) k_row() {
    int i = blockIdx.x;
    const float4* row = reinterpret_cast<const float4*>(g_E) + (size_t)i * N8;
    const float4* cv = reinterpret_cast<const float4*>(g_c);
    float acc = 0.0f;
    #pragma unroll 4
    for (int k = 0; k < 8; k++) {
        int idx = k * 128 + threadIdx.x;
        float4 raw = __ldcs(row + idx);
        const __half2* h = reinterpret_cast<const __half2*>(&raw);
        float4 c0 = __ldg(cv + idx * 2);
        float4 c1 = __ldg(cv + idx * 2 + 1);
        float2 f0 = __half22float2(h[0]);
        float2 f1 = __half22float2(h[1]);
        float2 f2 = __half22float2(h[2]);
        float2 f3 = __half22float2(h[3]);
        acc += f0.x * c0.x + f0.y * c0.y + f1.x * c0.z + f1.y * c0.w
             + f2.x * c1.x + f2.y * c1.y + f3.x * c1.z + f3.y * c1.w;
    }
    __shared__ float sm[4];
    #pragma unroll
    for (int o = 16; o > 0; o >>= 1) acc += __shfl_down_sync(0xffffffffu, acc, o);
    int lane = threadIdx.x & 31, wid = threadIdx.x >> 5;
    if (lane == 0) sm[wid] = acc;
    __syncthreads();
    if (threadIdx.x == 0) {
        float s = sm[0] + sm[1] + sm[2] + sm[3];
        float r = g_r[i];
        g_r[i] = r / (r * s + EPSC);
    }
}

// ---------------- col pass: partial t_j over 32-row chunk, 8 cols/thread ----------------
// 1024 blocks = 4 col-strips (2048 cols) x 256 row-chunks (32 rows); 256 threads
__global__ void __launch_bounds__(256) k_col() {
    int strip = blockIdx.x & 3;
    int chunk = blockIdx.x >> 2;
    int i0 = chunk * 32;
    __shared__ float rs[32];
    if (threadIdx.x < 32) rs[threadIdx.x] = g_r[i0 + threadIdx.x];
    __syncthreads();
    int j = strip * 2048 + threadIdx.x * 8;
    const float4* p = reinterpret_cast<const float4*>(g_E) + (size_t)i0 * N8 + (j >> 3);
    float a0 = 0, a1 = 0, a2 = 0, a3 = 0, a4 = 0, a5 = 0, a6 = 0, a7 = 0;
    #pragma unroll 4
    for (int i = 0; i < 32; i++) {
        float4 raw = __ldcs(p + (size_t)i * N8);
        const __half2* h = reinterpret_cast<const __half2*>(&raw);
        float rv = rs[i];
        float2 f0 = __half22float2(h[0]);
        float2 f1 = __half22float2(h[1]);
        float2 f2 = __half22float2(h[2]);
        float2 f3 = __half22float2(h[3]);
        a0 = fmaf(rv, f0.x, a0);  a1 = fmaf(rv, f0.y, a1);
        a2 = fmaf(rv, f1.x, a2);  a3 = fmaf(rv, f1.y, a3);
        a4 = fmaf(rv, f2.x, a4);  a5 = fmaf(rv, f2.y, a5);
        a6 = fmaf(rv, f3.x, a6);  a7 = fmaf(rv, f3.y, a7);
    }
    float4* o = reinterpret_cast<float4*>(&g_tpart[chunk][j]);
    o[0] = make_float4(a0, a1, a2, a3);
    o[1] = make_float4(a4, a5, a6, a7);
}

// ---------------- column reduce stage 1: 256 -> 16 partials ----------------
__global__ void k_cred1() {
    int j = blockIdx.x * 256 + threadIdx.x;
    int k0 = blockIdx.y * 16;
    float t = 0.0f;
    #pragma unroll
    for (int k = 0; k < 16; k++) t += __ldcs(&g_tpart[k0 + k][j]);
    g_t2[blockIdx.y][j] = t;
}

// ---------------- column reduce stage 2 + c update ----------------
__global__ void k_cred2() {
    int j = blockIdx.x * 256 + threadIdx.x;
    float t = 0.0f;
    #pragma unroll
    for (int k = 0; k < 16; k++) t += g_t2[k][j];
    float cv = g_c[j];
    g_c[j] = cv / (cv * t + EPSC);
}

// ---------------- final: out_ij = r_i * E_ij * c_j ----------------
// block = 2048 contiguous elems = quarter row -> single r per block
__global__ void __launch_bounds__(256) k_final(float* __restrict__ out) {
    size_t base = ((size_t)blockIdx.x * 256 + threadIdx.x) * 8;
    int i = blockIdx.x >> 2;
    int j = (int)(base & (N - 1));
    float r = __ldg(&g_r[i]);
    float4 raw = __ldcs(reinterpret_cast<const float4*>(g_E) + base / 8);
    const __half2* h = reinterpret_cast<const __half2*>(&raw);
    float4 c0 = __ldg(reinterpret_cast<const float4*>(g_c + j));
    float4 c1 = __ldg(reinterpret_cast<const float4*>(g_c + j + 4));
    float2 f0 = __half22float2(h[0]);
    float2 f1 = __half22float2(h[1]);
    float2 f2 = __half22float2(h[2]);
    float2 f3 = __half22float2(h[3]);
    float4 o0, o1;
    o0.x = r * f0.x * c0.x;  o0.y = r * f0.y * c0.y;
    o0.z = r * f1.x * c0.z;  o0.w = r * f1.y * c0.w;
    o1.x = r * f2.x * c1.x;  o1.y = r * f2.y * c1.y;
    o1.z = r * f3.x * c1.z;  o1.w = r * f3.y * c1.w;
    __stcs(reinterpret_cast<float4*>(out + base), o0);
    __stcs(reinterpret_cast<float4*>(out + base + 4), o1);
}

extern "C" void kernel_launch(void* const* d_in, const int* in_sizes, int n_in,
                              void* d_out, int out_size) {
    const float* W = (const float*)d_in[0];
    float* out = (float*)d_out;
    (void)in_sizes; (void)n_in; (void)out_size;

    const int ELEM_BLOCKS = (int)(((size_t)N * N) / (256 * 8));  // 32768

    k_exp<<<ELEM_BLOCKS, 256>>>(W);          // E = exp(W) + fused row-1 sums
    k_r1<<<N / 256, 256>>>();                // r1 = 1/(s+eps), c = 1
    for (int it = 0; it < ITERS; it++) {
        if (it > 0) k_row<<<N, 128>>>();     // row pass (iter 1 fused into k_exp)
        k_col<<<1024, 256>>>();              // col partials
        k_cred1<<<dim3(32, 16), 256>>>();    // reduce 256 -> 16
        k_cred2<<<N / 256, 256>>>();         // reduce 16 -> 1, update c
    }
    k_final<<<ELEM_BLOCKS, 256>>>(out);
}